// round 3
// baseline (speedup 1.0000x reference)
#include <cuda_runtime.h>
#include <cuda_fp16.h>

// ---------------- problem-size constants (fixed by the dataset) -------------
#define N_MAX   100032      // >= 100000 nodes
#define E_PAD   2001600     // E + 4*N padding headroom (1.6M + 400K)
#define D       50          // attrs
#define STRH    64          // padded row stride of fp16 buffers (64 halves = 128B)
#define NITER   30
#define SCAN_B  256

// ---------------- static device scratch (no allocations allowed) ------------
__device__ int    g_deg[N_MAX];
__device__ int    g_offs[N_MAX + 1];     // padded-CSR exclusive offsets (mult of 4)
__device__ int    g_cursor[N_MAX];
__device__ int    g_partial[512];
__device__ int    g_csr[E_PAD];          // col*STRH (half offset); dummies -> row n
__device__ float  g_dinv[N_MAX];
__device__ unsigned char g_isknown[N_MAX];
__device__ float  g_meansum[64];
__device__ float  g_mean[64];            // pads [50,64) stay 0 forever
__device__ float  g_alpha[64];
__device__ float  g_oma[64];
__device__ float  g_beta[64];
__device__ float  g_omb[64];
__device__ float  g_colsum[(NITER + 1) * 64];
__device__ int    g_need_colmean;
__device__ int    g_need_beta;
// zero-initialized; rows >= n are NEVER written, so dummy gathers read 0.
__device__ __half g_bufA[(size_t)N_MAX * STRH];
__device__ __half g_bufB[(size_t)N_MAX * STRH];

// ---------------- prologue kernels -------------------------------------------
__global__ void k_zero(int n) {
    int i = blockIdx.x * blockDim.x + threadIdx.x;
    if (i < n) { g_deg[i] = 0; g_isknown[i] = 0; }
    if (i < 64) g_meansum[i] = 0.f;
    if (i < (NITER + 1) * 64) g_colsum[i] = 0.f;
}

// degree histogram + isknown flags + mean partial sums (independent work)
__global__ void k_deg_known_mean(const int* __restrict__ row,
                                 const int* __restrict__ km,
                                 const float* __restrict__ x, int E, int K) {
    int i = blockIdx.x * blockDim.x + threadIdx.x;
    if (i < E) atomicAdd(&g_deg[row[i]], 1);
    if (i < K) g_isknown[km[i]] = 1;
    if (blockIdx.x < 100) {
        __shared__ float sm[64];
        if (threadIdx.x < 64) sm[threadIdx.x] = 0.f;
        __syncthreads();
        int lane = threadIdx.x & 31;
        int w  = (blockIdx.x * blockDim.x + threadIdx.x) >> 5;
        int nw = (100 * blockDim.x) >> 5;
        float2 acc = make_float2(0.f, 0.f);
        for (int k = w; k < K; k += nw) {
            int idx = km[k];
            if (lane < 25) {
                float2 vv = *(const float2*)(x + (size_t)idx * D + 2 * lane);
                acc.x += vv.x; acc.y += vv.y;
            }
        }
        if (lane < 25) {
            atomicAdd(&sm[2 * lane],     acc.x);
            atomicAdd(&sm[2 * lane + 1], acc.y);
        }
        __syncthreads();
        if (threadIdx.x < D) atomicAdd(&g_meansum[threadIdx.x], sm[threadIdx.x]);
    }
}

// dinv + block-level exclusive scan of padded degree ((deg+3)&~3)
__global__ void k_scan1(int n) {
    __shared__ int s[SCAN_B];
    int i = blockIdx.x * SCAN_B + threadIdx.x;
    int dg = (i < n) ? g_deg[i] : 0;
    if (i < n) g_dinv[i] = (dg > 0) ? rsqrtf((float)dg) : 0.f;
    int v = (dg + 3) & ~3;                      // padded length
    s[threadIdx.x] = v;
    __syncthreads();
    for (int d = 1; d < SCAN_B; d <<= 1) {
        int t = (threadIdx.x >= d) ? s[threadIdx.x - d] : 0;
        __syncthreads();
        s[threadIdx.x] += t;
        __syncthreads();
    }
    if (i < n) g_offs[i] = s[threadIdx.x] - v;   // exclusive (within block)
    if (threadIdx.x == SCAN_B - 1) g_partial[blockIdx.x] = s[SCAN_B - 1];
}

// scan of block totals + parameter computation (single block)
__global__ void k_scan2_params(int nb, const float* __restrict__ eta,
                               const float* __restrict__ theta, int n, int K) {
    __shared__ int s[512];
    __shared__ int fc, fb;
    int v = (threadIdx.x < nb) ? g_partial[threadIdx.x] : 0;
    s[threadIdx.x] = v;
    if (threadIdx.x == 0) { fc = 0; fb = 0; }
    __syncthreads();
    for (int d = 1; d < 512; d <<= 1) {
        int t = (threadIdx.x >= d) ? s[threadIdx.x - d] : 0;
        __syncthreads();
        s[threadIdx.x] += t;
        __syncthreads();
    }
    if (threadIdx.x < nb) g_partial[threadIdx.x] = s[threadIdx.x] - v;  // exclusive
    int d = threadIdx.x;
    if (d < D) {
        g_mean[d] = g_meansum[d] / (float)K;
        float nf = (float)n;
        float a  = (nf - 1.f) / (theta[d] * nf + (nf - 1.f));
        float ia = 1.f / a;
        float b  = ia / (ia + eta[d]);
        g_alpha[d] = a;  g_oma[d] = 1.f - a;
        g_beta[d]  = b;  g_omb[d] = 1.f - b;
        if (a != 1.f) atomicExch(&fc, 1);
        if (b != 1.f) atomicExch(&fb, 1);
    }
    __syncthreads();
    if (threadIdx.x == 0) { g_need_colmean = fc; g_need_beta = fb; }
}

// finalize offsets + cursors
__global__ void k_scan3(int n, int Epad_total) {
    int i = blockIdx.x * SCAN_B + threadIdx.x;
    if (i < n) {
        int o = g_offs[i] + g_partial[blockIdx.x];
        g_offs[i] = o;
        g_cursor[i] = o;
    }
    if (i == 0) g_offs[n] = Epad_total;
}

// CSR scatter: entry = col*STRH only (weights folded out)
__global__ void k_scatter(const int* __restrict__ row, const int* __restrict__ col, int E) {
    int e = blockIdx.x * blockDim.x + threadIdx.x;
    if (e < E) {
        int r = row[e];
        int p = atomicAdd(&g_cursor[r], 1);
        g_csr[p] = col[e] * STRH;
    }
}

// fill padding tail of each row with dummy entries pointing at zero row n
__global__ void k_fill(int n) {
    int i = blockIdx.x * blockDim.x + threadIdx.x;
    if (i < n) {
        int end  = g_offs[i + 1];
        int dummy = n * STRH;
        for (int j = g_offs[i] + g_deg[i]; j < end; ++j) g_csr[j] = dummy;
    }
}

// y0 = dinv * ((known ? x : 0) - mean)  -> fp16 buffer; colsum[0] of out0 if needed
__global__ void k_init(const float* __restrict__ x, int n) {
    int gw   = (blockIdx.x * blockDim.x + threadIdx.x) >> 5;
    int lane = threadIdx.x & 31;
    __shared__ float cs[64];
    int needc = g_need_colmean;
    if (needc) { if (threadIdx.x < 64) cs[threadIdx.x] = 0.f; __syncthreads(); }
    float2 v = make_float2(0.f, 0.f);
    if (gw < n) {
        if (lane < 25 && g_isknown[gw])
            v = *(const float2*)(x + (size_t)gw * D + 2 * lane);
        float2 m = ((const float2*)g_mean)[lane];
        v.x -= m.x; v.y -= m.y;
        float di = g_dinv[gw];
        if (lane < 25)
            *(__half2*)(g_bufA + (size_t)gw * STRH + 2 * lane) =
                __floats2half2_rn(di * v.x, di * v.y);
    }
    if (needc) {
        if (gw < n && lane < 25) {
            atomicAdd(&cs[2 * lane],     v.x);
            atomicAdd(&cs[2 * lane + 1], v.y);
        }
        __syncthreads();
        if (threadIdx.x < D) atomicAdd(&g_colsum[threadIdx.x], cs[threadIdx.x]);
    }
}

// ---------------- the hot loop: one propagation step ------------------------
// warp-per-node; lanes 0..24 own a float2 of the 50 attrs. Buffers hold
// y = dinv * out. out_new[r] = dinv[r] * sum_{c in N(r)} y[c]; store dinv*out_new.
__global__ __launch_bounds__(256) void k_iter(const float* __restrict__ x,
                                              float* __restrict__ fout,
                                              int n, float invn, int t, int last) {
    int gw   = (blockIdx.x * blockDim.x + threadIdx.x) >> 5;
    int lane = threadIdx.x & 31;
    __shared__ float cs[64];
    const int needc = g_need_colmean;
    if (needc) { if (threadIdx.x < 64) cs[threadIdx.x] = 0.f; __syncthreads(); }

    const __half* in  = (t & 1) ? g_bufB : g_bufA;
    __half*       out = (t & 1) ? g_bufA : g_bufB;
    const float* cs_in  = g_colsum + t * 64;
    float*       cs_out = g_colsum + (t + 1) * 64;

    float2 v = make_float2(0.f, 0.f);
    if (gw < n) {
        int s = g_offs[gw], e = g_offs[gw + 1];   // 16B aligned, length mult of 4
        const __half* inp = in + 2 * lane;
        float2 acc = make_float2(0.f, 0.f);
        int i = s;
        for (; i + 8 <= e; i += 8) {
            int4 c0 = *(const int4*)(g_csr + i);
            int4 c1 = *(const int4*)(g_csr + i + 4);
            float2 v0 = __half22float2(*(const __half2*)(inp + c0.x));
            float2 v1 = __half22float2(*(const __half2*)(inp + c0.y));
            float2 v2 = __half22float2(*(const __half2*)(inp + c0.z));
            float2 v3 = __half22float2(*(const __half2*)(inp + c0.w));
            float2 v4 = __half22float2(*(const __half2*)(inp + c1.x));
            float2 v5 = __half22float2(*(const __half2*)(inp + c1.y));
            float2 v6 = __half22float2(*(const __half2*)(inp + c1.z));
            float2 v7 = __half22float2(*(const __half2*)(inp + c1.w));
            acc.x += v0.x + v1.x + v2.x + v3.x + v4.x + v5.x + v6.x + v7.x;
            acc.y += v0.y + v1.y + v2.y + v3.y + v4.y + v5.y + v6.y + v7.y;
        }
        for (; i < e; i += 4) {
            int4 c0 = *(const int4*)(g_csr + i);
            float2 v0 = __half22float2(*(const __half2*)(inp + c0.x));
            float2 v1 = __half22float2(*(const __half2*)(inp + c0.y));
            float2 v2 = __half22float2(*(const __half2*)(inp + c0.z));
            float2 v3 = __half22float2(*(const __half2*)(inp + c0.w));
            acc.x += v0.x + v1.x + v2.x + v3.x;
            acc.y += v0.y + v1.y + v2.y + v3.y;
        }
        float di = g_dinv[gw];
        float2 a = ((const float2*)g_alpha)[lane];
        v.x = a.x * (di * acc.x);
        v.y = a.y * (di * acc.y);
        if (needc) {
            float2 om = ((const float2*)g_oma)[lane];
            v.x = fmaf(om.x, cs_in[2 * lane]     * invn, v.x);
            v.y = fmaf(om.y, cs_in[2 * lane + 1] * invn, v.y);
        }
        if (g_need_beta && g_isknown[gw]) {
            float2 b  = ((const float2*)g_beta)[lane];
            float2 ob = ((const float2*)g_omb)[lane];
            float2 m  = ((const float2*)g_mean)[lane];
            float2 xv = make_float2(0.f, 0.f);
            if (lane < 25) xv = *(const float2*)(x + (size_t)gw * D + 2 * lane);
            v.x = b.x * v.x + ob.x * (xv.x - m.x);
            v.y = b.y * v.y + ob.y * (xv.y - m.y);
        }
        if (last) {
            float2 m = ((const float2*)g_mean)[lane];
            if (lane < 25)
                *(float2*)(fout + (size_t)gw * D + 2 * lane) =
                    make_float2(v.x + m.x, v.y + m.y);
        } else {
            if (lane < 25)
                *(__half2*)(out + (size_t)gw * STRH + 2 * lane) =
                    __floats2half2_rn(di * v.x, di * v.y);
        }
    }
    if (needc && !last) {
        if (gw < n && lane < 25) {
            atomicAdd(&cs[2 * lane],     v.x);
            atomicAdd(&cs[2 * lane + 1], v.y);
        }
        __syncthreads();
        if (threadIdx.x < D) atomicAdd(&cs_out[threadIdx.x], cs[threadIdx.x]);
    }
}

// ---------------- launcher ---------------------------------------------------
extern "C" void kernel_launch(void* const* d_in, const int* in_sizes, int n_in,
                              void* d_out, int out_size) {
    const float* x     = (const float*)d_in[0];
    const float* eta   = (const float*)d_in[1];
    const float* theta = (const float*)d_in[2];
    const int*   ei    = (const int*)d_in[3];
    const int*   km    = (const int*)d_in[4];

    int dd = in_sizes[1];              // 50
    int n  = in_sizes[0] / dd;         // 100000
    int E  = in_sizes[3] / 2;          // 1600000
    int K  = in_sizes[4];              // 50000
    const int* row = ei;
    const int* col = ei + E;

    const int TB = 256;
    int nbN = (n + TB - 1) / TB;
    int nbE = (E + TB - 1) / TB;
    int nbW = (n * 32 + TB - 1) / TB;  // warp-per-node grids

    k_zero          <<<nbN, TB>>>(n);
    k_deg_known_mean<<<nbE, TB>>>(row, km, x, E, K);
    k_scan1         <<<nbN, TB>>>(n);
    k_scan2_params  <<<1, 512>>>(nbN, eta, theta, n, K);
    k_scan3         <<<nbN, TB>>>(n, E_PAD);  // offs[n] only bounds the fill of last node
    k_scatter       <<<nbE, TB>>>(row, col, E);
    k_fill          <<<nbN, TB>>>(n);
    k_init          <<<nbW, TB>>>(x, n);

    // NOTE: offs[n] must be the true padded total, not E_PAD, for the last
    // node's edge loop. Fix: recompute it exactly — it equals offs[n-1] +
    // padded deg of node n-1; k_fill reads offs[n] too. We instead set it
    // correctly here via a tiny kernel-free trick: k_scan3 wrote E_PAD which
    // over-runs. To stay safe, g_csr is sized E_PAD and k_fill fills the whole
    // tail of the last node up to offs[n]; entries there are dummies (zero
    // row), so the last node's sum is unaffected, just a few extra reads.

    float invn = 1.f / (float)n;
    for (int t = 0; t < NITER; ++t) {
        k_iter<<<nbW, TB>>>(x, (float*)d_out, n, invn, t, (t == NITER - 1) ? 1 : 0);
    }
}

// round 4
// speedup vs baseline: 220.3088x; 220.3088x over previous
#include <cuda_runtime.h>
#include <cuda_fp16.h>

// ---------------- problem-size constants (fixed by the dataset) -------------
#define N_MAX   100032      // >= 100000 nodes
#define E_PAD   2001600     // E + 4*N padding headroom (1.6M + 400K)
#define D       50          // attrs
#define STRH    64          // padded row stride of fp16 buffers (64 halves = 128B)
#define NITER   30
#define SCAN_B  256

// ---------------- static device scratch (no allocations allowed) ------------
__device__ int    g_deg[N_MAX];          // g_deg[n] stays 0 (never incremented)
__device__ int    g_offs[N_MAX + 1];     // padded-CSR exclusive offsets (mult of 4)
__device__ int    g_cursor[N_MAX];
__device__ int    g_partial[512];
__device__ int    g_csr[E_PAD];          // col*STRH (half offset); dummies -> row n
__device__ float  g_dinv[N_MAX];
__device__ unsigned char g_isknown[N_MAX];
__device__ float  g_meansum[64];
__device__ float  g_mean[64];            // pads [50,64) stay 0 forever
__device__ float  g_alpha[64];
__device__ float  g_oma[64];
__device__ float  g_beta[64];
__device__ float  g_omb[64];
__device__ float  g_colsum[(NITER + 1) * 64];
__device__ int    g_need_colmean;
__device__ int    g_need_beta;
// zero-initialized; rows >= n are NEVER written, so dummy gathers read 0.
__device__ __half g_bufA[(size_t)N_MAX * STRH];
__device__ __half g_bufB[(size_t)N_MAX * STRH];

// ---------------- prologue kernels -------------------------------------------
__global__ void k_zero(int n) {
    int i = blockIdx.x * blockDim.x + threadIdx.x;
    if (i < n) { g_deg[i] = 0; g_isknown[i] = 0; }
    if (i < 64) g_meansum[i] = 0.f;
    if (i < (NITER + 1) * 64) g_colsum[i] = 0.f;
}

// degree histogram + isknown flags + mean partial sums (independent work)
__global__ void k_deg_known_mean(const int* __restrict__ row,
                                 const int* __restrict__ km,
                                 const float* __restrict__ x, int E, int K) {
    int i = blockIdx.x * blockDim.x + threadIdx.x;
    if (i < E) atomicAdd(&g_deg[row[i]], 1);
    if (i < K) g_isknown[km[i]] = 1;
    if (blockIdx.x < 100) {
        __shared__ float sm[64];
        if (threadIdx.x < 64) sm[threadIdx.x] = 0.f;
        __syncthreads();
        int lane = threadIdx.x & 31;
        int w  = (blockIdx.x * blockDim.x + threadIdx.x) >> 5;
        int nw = (100 * blockDim.x) >> 5;
        float2 acc = make_float2(0.f, 0.f);
        for (int k = w; k < K; k += nw) {
            int idx = km[k];
            if (lane < 25) {
                float2 vv = *(const float2*)(x + (size_t)idx * D + 2 * lane);
                acc.x += vv.x; acc.y += vv.y;
            }
        }
        if (lane < 25) {
            atomicAdd(&sm[2 * lane],     acc.x);
            atomicAdd(&sm[2 * lane + 1], acc.y);
        }
        __syncthreads();
        if (threadIdx.x < D) atomicAdd(&g_meansum[threadIdx.x], sm[threadIdx.x]);
    }
}

// dinv + block-level exclusive scan of padded degree ((deg+3)&~3).
// Covers i in [0, n] inclusive: the virtual node i==n has degree 0, so its
// exclusive-scan position is the EXACT padded total -> g_offs[n].
__global__ void k_scan1(int n) {
    __shared__ int s[SCAN_B];
    int i = blockIdx.x * SCAN_B + threadIdx.x;
    int dg = (i < n) ? g_deg[i] : 0;
    if (i < n) g_dinv[i] = (dg > 0) ? rsqrtf((float)dg) : 0.f;
    int v = (dg + 3) & ~3;                      // padded length (0 for i>=n)
    s[threadIdx.x] = v;
    __syncthreads();
    for (int d = 1; d < SCAN_B; d <<= 1) {
        int t = (threadIdx.x >= d) ? s[threadIdx.x - d] : 0;
        __syncthreads();
        s[threadIdx.x] += t;
        __syncthreads();
    }
    if (i <= n) g_offs[i] = s[threadIdx.x] - v;   // exclusive (within block)
    if (threadIdx.x == SCAN_B - 1) g_partial[blockIdx.x] = s[SCAN_B - 1];
}

// scan of block totals + parameter computation (single block)
__global__ void k_scan2_params(int nb, const float* __restrict__ eta,
                               const float* __restrict__ theta, int n, int K) {
    __shared__ int s[512];
    __shared__ int fc, fb;
    int v = (threadIdx.x < nb) ? g_partial[threadIdx.x] : 0;
    s[threadIdx.x] = v;
    if (threadIdx.x == 0) { fc = 0; fb = 0; }
    __syncthreads();
    for (int d = 1; d < 512; d <<= 1) {
        int t = (threadIdx.x >= d) ? s[threadIdx.x - d] : 0;
        __syncthreads();
        s[threadIdx.x] += t;
        __syncthreads();
    }
    if (threadIdx.x < nb) g_partial[threadIdx.x] = s[threadIdx.x] - v;  // exclusive
    int d = threadIdx.x;
    if (d < D) {
        g_mean[d] = g_meansum[d] / (float)K;
        float nf = (float)n;
        float a  = (nf - 1.f) / (theta[d] * nf + (nf - 1.f));
        float ia = 1.f / a;
        float b  = ia / (ia + eta[d]);
        g_alpha[d] = a;  g_oma[d] = 1.f - a;
        g_beta[d]  = b;  g_omb[d] = 1.f - b;
        if (a != 1.f) atomicExch(&fc, 1);
        if (b != 1.f) atomicExch(&fb, 1);
    }
    __syncthreads();
    if (threadIdx.x == 0) { g_need_colmean = fc; g_need_beta = fb; }
}

// finalize offsets + cursors; i==n gets the exact padded total.
__global__ void k_scan3(int n) {
    int i = blockIdx.x * SCAN_B + threadIdx.x;
    if (i <= n) {
        int o = g_offs[i] + g_partial[blockIdx.x];
        g_offs[i] = o;
        if (i < n) g_cursor[i] = o;
    }
}

// CSR scatter: entry = col*STRH only (weights folded out)
__global__ void k_scatter(const int* __restrict__ row, const int* __restrict__ col, int E) {
    int e = blockIdx.x * blockDim.x + threadIdx.x;
    if (e < E) {
        int r = row[e];
        int p = atomicAdd(&g_cursor[r], 1);
        g_csr[p] = col[e] * STRH;
    }
}

// fill padding tail of each row (<= 3 entries) with dummies pointing at zero row n
__global__ void k_fill(int n) {
    int i = blockIdx.x * blockDim.x + threadIdx.x;
    if (i < n) {
        int end   = g_offs[i + 1];
        int dummy = n * STRH;
        for (int j = g_offs[i] + g_deg[i]; j < end; ++j) g_csr[j] = dummy;
    }
}

// y0 = dinv * ((known ? x : 0) - mean)  -> fp16 buffer; colsum[0] of out0 if needed
__global__ void k_init(const float* __restrict__ x, int n) {
    int gw   = (blockIdx.x * blockDim.x + threadIdx.x) >> 5;
    int lane = threadIdx.x & 31;
    __shared__ float cs[64];
    int needc = g_need_colmean;
    if (needc) { if (threadIdx.x < 64) cs[threadIdx.x] = 0.f; __syncthreads(); }
    float2 v = make_float2(0.f, 0.f);
    if (gw < n) {
        if (lane < 25 && g_isknown[gw])
            v = *(const float2*)(x + (size_t)gw * D + 2 * lane);
        float2 m = ((const float2*)g_mean)[lane];
        v.x -= m.x; v.y -= m.y;
        float di = g_dinv[gw];
        if (lane < 25)
            *(__half2*)(g_bufA + (size_t)gw * STRH + 2 * lane) =
                __floats2half2_rn(di * v.x, di * v.y);
    }
    if (needc) {
        if (gw < n && lane < 25) {
            atomicAdd(&cs[2 * lane],     v.x);
            atomicAdd(&cs[2 * lane + 1], v.y);
        }
        __syncthreads();
        if (threadIdx.x < D) atomicAdd(&g_colsum[threadIdx.x], cs[threadIdx.x]);
    }
}

// ---------------- the hot loop: one propagation step ------------------------
// warp-per-node; lanes 0..24 own a float2 of the 50 attrs. Buffers hold
// y = dinv * out. out_new[r] = dinv[r] * sum_{c in N(r)} y[c]; store dinv*out_new.
__global__ __launch_bounds__(256) void k_iter(const float* __restrict__ x,
                                              float* __restrict__ fout,
                                              int n, float invn, int t, int last) {
    int gw   = (blockIdx.x * blockDim.x + threadIdx.x) >> 5;
    int lane = threadIdx.x & 31;
    __shared__ float cs[64];
    const int needc = g_need_colmean;
    if (needc) { if (threadIdx.x < 64) cs[threadIdx.x] = 0.f; __syncthreads(); }

    const __half* in  = (t & 1) ? g_bufB : g_bufA;
    __half*       out = (t & 1) ? g_bufA : g_bufB;
    const float* cs_in  = g_colsum + t * 64;
    float*       cs_out = g_colsum + (t + 1) * 64;

    float2 v = make_float2(0.f, 0.f);
    if (gw < n) {
        int s = g_offs[gw], e = g_offs[gw + 1];   // 16B aligned, length mult of 4
        const __half* inp = in + 2 * lane;
        float2 acc = make_float2(0.f, 0.f);
        int i = s;
        for (; i + 8 <= e; i += 8) {
            int4 c0 = *(const int4*)(g_csr + i);
            int4 c1 = *(const int4*)(g_csr + i + 4);
            float2 v0 = __half22float2(*(const __half2*)(inp + c0.x));
            float2 v1 = __half22float2(*(const __half2*)(inp + c0.y));
            float2 v2 = __half22float2(*(const __half2*)(inp + c0.z));
            float2 v3 = __half22float2(*(const __half2*)(inp + c0.w));
            float2 v4 = __half22float2(*(const __half2*)(inp + c1.x));
            float2 v5 = __half22float2(*(const __half2*)(inp + c1.y));
            float2 v6 = __half22float2(*(const __half2*)(inp + c1.z));
            float2 v7 = __half22float2(*(const __half2*)(inp + c1.w));
            acc.x += v0.x + v1.x + v2.x + v3.x + v4.x + v5.x + v6.x + v7.x;
            acc.y += v0.y + v1.y + v2.y + v3.y + v4.y + v5.y + v6.y + v7.y;
        }
        for (; i < e; i += 4) {
            int4 c0 = *(const int4*)(g_csr + i);
            float2 v0 = __half22float2(*(const __half2*)(inp + c0.x));
            float2 v1 = __half22float2(*(const __half2*)(inp + c0.y));
            float2 v2 = __half22float2(*(const __half2*)(inp + c0.z));
            float2 v3 = __half22float2(*(const __half2*)(inp + c0.w));
            acc.x += v0.x + v1.x + v2.x + v3.x;
            acc.y += v0.y + v1.y + v2.y + v3.y;
        }
        float di = g_dinv[gw];
        float2 a = ((const float2*)g_alpha)[lane];
        v.x = a.x * (di * acc.x);
        v.y = a.y * (di * acc.y);
        if (needc) {
            float2 om = ((const float2*)g_oma)[lane];
            v.x = fmaf(om.x, cs_in[2 * lane]     * invn, v.x);
            v.y = fmaf(om.y, cs_in[2 * lane + 1] * invn, v.y);
        }
        if (g_need_beta && g_isknown[gw]) {
            float2 b  = ((const float2*)g_beta)[lane];
            float2 ob = ((const float2*)g_omb)[lane];
            float2 m  = ((const float2*)g_mean)[lane];
            float2 xv = make_float2(0.f, 0.f);
            if (lane < 25) xv = *(const float2*)(x + (size_t)gw * D + 2 * lane);
            v.x = b.x * v.x + ob.x * (xv.x - m.x);
            v.y = b.y * v.y + ob.y * (xv.y - m.y);
        }
        if (last) {
            float2 m = ((const float2*)g_mean)[lane];
            if (lane < 25)
                *(float2*)(fout + (size_t)gw * D + 2 * lane) =
                    make_float2(v.x + m.x, v.y + m.y);
        } else {
            if (lane < 25)
                *(__half2*)(out + (size_t)gw * STRH + 2 * lane) =
                    __floats2half2_rn(di * v.x, di * v.y);
        }
    }
    if (needc && !last) {
        if (gw < n && lane < 25) {
            atomicAdd(&cs[2 * lane],     v.x);
            atomicAdd(&cs[2 * lane + 1], v.y);
        }
        __syncthreads();
        if (threadIdx.x < D) atomicAdd(&cs_out[threadIdx.x], cs[threadIdx.x]);
    }
}

// ---------------- launcher ---------------------------------------------------
extern "C" void kernel_launch(void* const* d_in, const int* in_sizes, int n_in,
                              void* d_out, int out_size) {
    const float* x     = (const float*)d_in[0];
    const float* eta   = (const float*)d_in[1];
    const float* theta = (const float*)d_in[2];
    const int*   ei    = (const int*)d_in[3];
    const int*   km    = (const int*)d_in[4];

    int dd = in_sizes[1];              // 50
    int n  = in_sizes[0] / dd;         // 100000
    int E  = in_sizes[3] / 2;          // 1600000
    int K  = in_sizes[4];              // 50000
    const int* row = ei;
    const int* col = ei + E;

    const int TB = 256;
    int nbN  = (n + TB - 1) / TB;
    int nbN1 = (n + 1 + TB - 1) / TB;  // covers virtual node i == n
    int nbE  = (E + TB - 1) / TB;
    int nbW  = (n * 32 + TB - 1) / TB; // warp-per-node grids

    k_zero          <<<nbN, TB>>>(n);
    k_deg_known_mean<<<nbE, TB>>>(row, km, x, E, K);
    k_scan1         <<<nbN1, TB>>>(n);
    k_scan2_params  <<<1, 512>>>(nbN1, eta, theta, n, K);
    k_scan3         <<<nbN1, TB>>>(n);
    k_scatter       <<<nbE, TB>>>(row, col, E);
    k_fill          <<<nbN, TB>>>(n);
    k_init          <<<nbW, TB>>>(x, n);

    float invn = 1.f / (float)n;
    for (int t = 0; t < NITER; ++t) {
        k_iter<<<nbW, TB>>>(x, (float*)d_out, n, invn, t, (t == NITER - 1) ? 1 : 0);
    }
}

// round 6
// speedup vs baseline: 230.5327x; 1.0464x over previous
#include <cuda_runtime.h>
#include <cuda_fp16.h>

// ---------------- problem-size constants (fixed by the dataset) -------------
#define N_MAX   100032      // >= 100000 nodes
#define E_PAD   2001600     // E + 4*N padding headroom
#define D       50          // attrs
#define STRH    64          // padded row stride of fp16 buffers (64 halves = 128B)
#define NITER   30
#define SCAN_B  256

// ---------------- static device scratch (no allocations allowed) ------------
__device__ int    g_deg[N_MAX];          // g_deg[n] stays 0 (never incremented)
__device__ int    g_offs[N_MAX + 1];     // padded-CSR exclusive offsets (mult of 4)
__device__ int2   g_span[N_MAX];         // {start, end} per node (one 8B load)
__device__ int    g_cursor[N_MAX];
__device__ int    g_partial[512];
__device__ int    g_csr[E_PAD];          // col*STRH (half offset); dummies -> row n
__device__ float  g_dinv[N_MAX];
__device__ unsigned char g_isknown[N_MAX];
__device__ float  g_meansum[64];
__device__ float  g_mean[64];            // pads [50,64) stay 0 forever
__device__ float  g_alpha[64];
__device__ float  g_oma[64];
__device__ float  g_beta[64];
__device__ float  g_omb[64];
__device__ float  g_colsum[(NITER + 1) * 64];
__device__ int    g_need_colmean;        // set iff any alpha != 1  (oma != 0)
__device__ int    g_need_beta;
// zero-initialized; rows >= n are NEVER written, so dummy gathers read 0.
__device__ __half g_bufA[(size_t)N_MAX * STRH];
__device__ __half g_bufB[(size_t)N_MAX * STRH];

// ---------------- prologue kernels -------------------------------------------
__global__ void k_zero(int n) {
    int i = blockIdx.x * blockDim.x + threadIdx.x;
    if (i < n) { g_deg[i] = 0; g_isknown[i] = 0; }
    if (i < 64) g_meansum[i] = 0.f;
    if (i < (NITER + 1) * 64) g_colsum[i] = 0.f;
}

// degree histogram + isknown flags + mean partial sums (independent work)
__global__ void k_deg_known_mean(const int* __restrict__ row,
                                 const int* __restrict__ km,
                                 const float* __restrict__ x, int E, int K) {
    int i = blockIdx.x * blockDim.x + threadIdx.x;
    if (i < E) atomicAdd(&g_deg[row[i]], 1);
    if (i < K) g_isknown[km[i]] = 1;
    if (blockIdx.x < 100) {
        __shared__ float sm[64];
        if (threadIdx.x < 64) sm[threadIdx.x] = 0.f;
        __syncthreads();
        int lane = threadIdx.x & 31;
        int w  = (blockIdx.x * blockDim.x + threadIdx.x) >> 5;
        int nw = (100 * blockDim.x) >> 5;
        float2 acc = make_float2(0.f, 0.f);
        for (int k = w; k < K; k += nw) {
            int idx = km[k];
            if (lane < 25) {
                float2 vv = *(const float2*)(x + (size_t)idx * D + 2 * lane);
                acc.x += vv.x; acc.y += vv.y;
            }
        }
        if (lane < 25) {
            atomicAdd(&sm[2 * lane],     acc.x);
            atomicAdd(&sm[2 * lane + 1], acc.y);
        }
        __syncthreads();
        if (threadIdx.x < D) atomicAdd(&g_meansum[threadIdx.x], sm[threadIdx.x]);
    }
}

// dinv + block-level exclusive scan of padded degree ((deg+3)&~3).
// Covers i in [0, n]: virtual node i==n (deg 0) yields the exact padded total.
__global__ void k_scan1(int n) {
    __shared__ int s[SCAN_B];
    int i = blockIdx.x * SCAN_B + threadIdx.x;
    int dg = (i < n) ? g_deg[i] : 0;
    if (i < n) g_dinv[i] = (dg > 0) ? rsqrtf((float)dg) : 0.f;
    int v = (dg + 3) & ~3;
    s[threadIdx.x] = v;
    __syncthreads();
    for (int d = 1; d < SCAN_B; d <<= 1) {
        int t = (threadIdx.x >= d) ? s[threadIdx.x - d] : 0;
        __syncthreads();
        s[threadIdx.x] += t;
        __syncthreads();
    }
    if (i <= n) g_offs[i] = s[threadIdx.x] - v;
    if (threadIdx.x == SCAN_B - 1) g_partial[blockIdx.x] = s[SCAN_B - 1];
}

// scan of block totals + parameter computation (single block)
__global__ void k_scan2_params(int nb, const float* __restrict__ eta,
                               const float* __restrict__ theta, int n, int K) {
    __shared__ int s[512];
    __shared__ int fc, fb;
    int v = (threadIdx.x < nb) ? g_partial[threadIdx.x] : 0;
    s[threadIdx.x] = v;
    if (threadIdx.x == 0) { fc = 0; fb = 0; }
    __syncthreads();
    for (int d = 1; d < 512; d <<= 1) {
        int t = (threadIdx.x >= d) ? s[threadIdx.x - d] : 0;
        __syncthreads();
        s[threadIdx.x] += t;
        __syncthreads();
    }
    if (threadIdx.x < nb) g_partial[threadIdx.x] = s[threadIdx.x] - v;
    int d = threadIdx.x;
    if (d < D) {
        g_mean[d] = g_meansum[d] / (float)K;
        float nf = (float)n;
        float a  = (nf - 1.f) / (theta[d] * nf + (nf - 1.f));
        float ia = 1.f / a;
        float b  = ia / (ia + eta[d]);
        g_alpha[d] = a;  g_oma[d] = 1.f - a;
        g_beta[d]  = b;  g_omb[d] = 1.f - b;
        if (a != 1.f) atomicExch(&fc, 1);
        if (b != 1.f) atomicExch(&fb, 1);
    }
    __syncthreads();
    if (threadIdx.x == 0) { g_need_colmean = fc; g_need_beta = fb; }
}

// finalize offsets + cursors; i==n gets the exact padded total.
__global__ void k_scan3(int n) {
    int i = blockIdx.x * SCAN_B + threadIdx.x;
    if (i <= n) {
        int o = g_offs[i] + g_partial[blockIdx.x];
        g_offs[i] = o;
        if (i < n) g_cursor[i] = o;
    }
}

// CSR scatter: entry = col*STRH only (weights folded out)
__global__ void k_scatter(const int* __restrict__ row, const int* __restrict__ col, int E) {
    int e = blockIdx.x * blockDim.x + threadIdx.x;
    if (e < E) {
        int r = row[e];
        int p = atomicAdd(&g_cursor[r], 1);
        g_csr[p] = col[e] * STRH;
    }
}

// fused: pad-fill (<=3 dummies/row) + span build + y0 init (+ colsum[0] if needed)
__global__ void k_init(const float* __restrict__ x, int n) {
    int tidg = blockIdx.x * blockDim.x + threadIdx.x;
    // linear-thread part: fill pad tail, build span (disjoint from scatter's writes)
    if (tidg < n) {
        int s  = g_offs[tidg];
        int e2 = g_offs[tidg + 1];
        g_span[tidg] = make_int2(s, e2);
        int dummy = n * STRH;
        for (int j = s + g_deg[tidg]; j < e2; ++j) g_csr[j] = dummy;
    }
    // warp-per-node part: y0 = dinv * ((known ? x : 0) - mean)
    int gw   = tidg >> 5;
    int lane = threadIdx.x & 31;
    __shared__ float cs[64];
    int needc = g_need_colmean;
    if (needc) { if (threadIdx.x < 64) cs[threadIdx.x] = 0.f; __syncthreads(); }
    float2 v = make_float2(0.f, 0.f);
    if (gw < n) {
        if (lane < 25 && g_isknown[gw])
            v = *(const float2*)(x + (size_t)gw * D + 2 * lane);
        float2 m = ((const float2*)g_mean)[lane];
        v.x -= m.x; v.y -= m.y;
        float di = g_dinv[gw];
        if (lane < 25)
            *(__half2*)(g_bufA + (size_t)gw * STRH + 2 * lane) =
                __floats2half2_rn(di * v.x, di * v.y);
    }
    if (needc) {
        if (gw < n && lane < 25) {
            atomicAdd(&cs[2 * lane],     v.x);
            atomicAdd(&cs[2 * lane + 1], v.y);
        }
        __syncthreads();
        if (threadIdx.x < D) atomicAdd(&g_colsum[threadIdx.x], cs[threadIdx.x]);
    }
}

// ---------------- the hot loop: one propagation step ------------------------
// warp-per-node; lanes 0..24 own a float2 of the 50 attrs. Buffers hold
// y = dinv * out. out_new[r] = dinv[r] * sum_{c in N(r)} y[c]; store dinv*out_new.
// When need_colmean==0 (<=> alpha==1 exactly), the alpha load+mul is skipped.
__global__ __launch_bounds__(256) void k_iter(const float* __restrict__ x,
                                              float* __restrict__ fout,
                                              int n, float invn, int t, int last) {
    int gw   = (blockIdx.x * blockDim.x + threadIdx.x) >> 5;
    int lane = threadIdx.x & 31;
    __shared__ float cs[64];
    const int needc = g_need_colmean;
    if (needc) { if (threadIdx.x < 64) cs[threadIdx.x] = 0.f; __syncthreads(); }

    const __half* in  = (t & 1) ? g_bufB : g_bufA;
    __half*       out = (t & 1) ? g_bufA : g_bufB;
    const float* cs_in  = g_colsum + t * 64;
    float*       cs_out = g_colsum + (t + 1) * 64;

    float2 v = make_float2(0.f, 0.f);
    if (gw < n) {
        int2 sp = g_span[gw];                     // one 8B uniform load
        int s = sp.x, e = sp.y;                   // 16B aligned, mult of 4
        const __half* inp = in + 2 * lane;
        float2 acc = make_float2(0.f, 0.f);
        int i = s;
        for (; i + 8 <= e; i += 8) {
            int4 c0 = *(const int4*)(g_csr + i);
            int4 c1 = *(const int4*)(g_csr + i + 4);
            float2 v0 = __half22float2(*(const __half2*)(inp + c0.x));
            float2 v1 = __half22float2(*(const __half2*)(inp + c0.y));
            float2 v2 = __half22float2(*(const __half2*)(inp + c0.z));
            float2 v3 = __half22float2(*(const __half2*)(inp + c0.w));
            float2 v4 = __half22float2(*(const __half2*)(inp + c1.x));
            float2 v5 = __half22float2(*(const __half2*)(inp + c1.y));
            float2 v6 = __half22float2(*(const __half2*)(inp + c1.z));
            float2 v7 = __half22float2(*(const __half2*)(inp + c1.w));
            acc.x += v0.x + v1.x + v2.x + v3.x + v4.x + v5.x + v6.x + v7.x;
            acc.y += v0.y + v1.y + v2.y + v3.y + v4.y + v5.y + v6.y + v7.y;
        }
        for (; i < e; i += 4) {
            int4 c0 = *(const int4*)(g_csr + i);
            float2 v0 = __half22float2(*(const __half2*)(inp + c0.x));
            float2 v1 = __half22float2(*(const __half2*)(inp + c0.y));
            float2 v2 = __half22float2(*(const __half2*)(inp + c0.z));
            float2 v3 = __half22float2(*(const __half2*)(inp + c0.w));
            acc.x += v0.x + v1.x + v2.x + v3.x;
            acc.y += v0.y + v1.y + v2.y + v3.y;
        }
        float di = g_dinv[gw];
        if (needc) {
            float2 a  = ((const float2*)g_alpha)[lane];
            float2 om = ((const float2*)g_oma)[lane];
            v.x = fmaf(a.x, di * acc.x, om.x * (cs_in[2 * lane]     * invn));
            v.y = fmaf(a.y, di * acc.y, om.y * (cs_in[2 * lane + 1] * invn));
        } else {
            v.x = di * acc.x;                     // alpha == 1 exactly
            v.y = di * acc.y;
        }
        if (g_need_beta && g_isknown[gw]) {
            float2 b  = ((const float2*)g_beta)[lane];
            float2 ob = ((const float2*)g_omb)[lane];
            float2 m  = ((const float2*)g_mean)[lane];
            float2 xv = make_float2(0.f, 0.f);
            if (lane < 25) xv = *(const float2*)(x + (size_t)gw * D + 2 * lane);
            v.x = b.x * v.x + ob.x * (xv.x - m.x);
            v.y = b.y * v.y + ob.y * (xv.y - m.y);
        }
        if (last) {
            float2 m = ((const float2*)g_mean)[lane];
            if (lane < 25)
                *(float2*)(fout + (size_t)gw * D + 2 * lane) =
                    make_float2(v.x + m.x, v.y + m.y);
        } else {
            if (lane < 25)
                *(__half2*)(out + (size_t)gw * STRH + 2 * lane) =
                    __floats2half2_rn(di * v.x, di * v.y);
        }
    }
    if (needc && !last) {
        if (gw < n && lane < 25) {
            atomicAdd(&cs[2 * lane],     v.x);
            atomicAdd(&cs[2 * lane + 1], v.y);
        }
        __syncthreads();
        if (threadIdx.x < D) atomicAdd(&cs_out[threadIdx.x], cs[threadIdx.x]);
    }
}

// ---------------- launcher ---------------------------------------------------
extern "C" void kernel_launch(void* const* d_in, const int* in_sizes, int n_in,
                              void* d_out, int out_size) {
    const float* x     = (const float*)d_in[0];
    const float* eta   = (const float*)d_in[1];
    const float* theta = (const float*)d_in[2];
    const int*   ei    = (const int*)d_in[3];
    const int*   km    = (const int*)d_in[4];

    int dd = in_sizes[1];              // 50
    int n  = in_sizes[0] / dd;         // 100000
    int E  = in_sizes[3] / 2;          // 1600000
    int K  = in_sizes[4];              // 50000
    const int* row = ei;
    const int* col = ei + E;

    const int TB = 256;
    int nbN  = (n + TB - 1) / TB;
    int nbN1 = (n + 1 + TB - 1) / TB;  // covers virtual node i == n
    int nbE  = (E + TB - 1) / TB;
    int nbW  = (n * 32 + TB - 1) / TB; // warp-per-node grids

    k_zero          <<<nbN, TB>>>(n);
    k_deg_known_mean<<<nbE, TB>>>(row, km, x, E, K);
    k_scan1         <<<nbN1, TB>>>(n);
    k_scan2_params  <<<1, 512>>>(nbN1, eta, theta, n, K);
    k_scan3         <<<nbN1, TB>>>(n);
    k_scatter       <<<nbE, TB>>>(row, col, E);
    k_init          <<<nbW, TB>>>(x, n);

    float invn = 1.f / (float)n;
    for (int t = 0; t < NITER; ++t) {
        k_iter<<<nbW, TB>>>(x, (float*)d_out, n, invn, t, (t == NITER - 1) ? 1 : 0);
    }
}